// round 3
// baseline (speedup 1.0000x reference)
#include <cuda_runtime.h>
#include <cuda_bf16.h>

// ChannelSelfAttention: B=4,H=512,W=256, C=2.
// 2048 independent rows; per row: rank-2 attention over 256 positions.
// One block per (b,h) row, one thread per w position.

#define WIDTH 256

__global__ __launch_bounds__(WIDTH) void channel_attn_kernel(
    const float* __restrict__ x1, const float* __restrict__ x2,
    const float* __restrict__ wq, const float* __restrict__ bq,
    const float* __restrict__ wk, const float* __restrict__ bk,
    const float* __restrict__ wv, const float* __restrict__ bv,
    float* __restrict__ out, int n_elem)
{
    __shared__ float4 kv[WIDTH];  // {k0, k1, v0, v1} per position u

    const int row  = blockIdx.x;
    const int w    = threadIdx.x;
    const int base = row * WIDTH;

    const float xa = x1[base + w];
    const float xb = x2[base + w];

    // tiny weights: read via L2/L1 (16 floats, fully cached across blocks)
    const float q00 = __ldg(&wq[0]), q01 = __ldg(&wq[1]);
    const float q10 = __ldg(&wq[2]), q11 = __ldg(&wq[3]);
    const float k00 = __ldg(&wk[0]), k01 = __ldg(&wk[1]);
    const float k10 = __ldg(&wk[2]), k11 = __ldg(&wk[3]);
    const float v00 = __ldg(&wv[0]), v01 = __ldg(&wv[1]);
    const float v10 = __ldg(&wv[2]), v11 = __ldg(&wv[3]);
    const float bq0 = __ldg(&bq[0]), bq1 = __ldg(&bq[1]);
    const float bk0 = __ldg(&bk[0]), bk1 = __ldg(&bk[1]);
    const float bv0 = __ldg(&bv[0]), bv1 = __ldg(&bv[1]);

    const float LOG2E = 1.4426950408889634f;

    // q for this w, pre-scaled by log2e so score -> exp2 directly
    const float a0 = (fmaf(q00, xa, fmaf(q01, xb, bq0))) * LOG2E;
    const float a1 = (fmaf(q10, xa, fmaf(q11, xb, bq1))) * LOG2E;

    // k, v for position u == w, publish to shared
    float4 mine;
    mine.x = fmaf(k00, xa, fmaf(k01, xb, bk0));
    mine.y = fmaf(k10, xa, fmaf(k11, xb, bk1));
    mine.z = fmaf(v00, xa, fmaf(v01, xb, bv0));
    mine.w = fmaf(v10, xa, fmaf(v11, xb, bv1));
    kv[w] = mine;
    __syncthreads();

    float den = 0.f, n0 = 0.f, n1 = 0.f;

#pragma unroll 16
    for (int u = 0; u < WIDTH; ++u) {
        float4 t = kv[u];                       // broadcast LDS.128
        float s = fmaf(a0, t.x, a1 * t.y);      // score in log2 domain
        float e;
        asm("ex2.approx.ftz.f32 %0, %1;" : "=f"(e) : "f"(s));
        den += e;
        n0 = fmaf(e, t.z, n0);
        n1 = fmaf(e, t.w, n1);
    }

    const float inv = 1.0f / den;               // once per thread
    out[base + w]          = fmaf(n0, inv, xa); // out1 = x1 + attn0
    out[n_elem + base + w] = fmaf(n1, inv, xb); // out2 = x2 + attn1
}

extern "C" void kernel_launch(void* const* d_in, const int* in_sizes, int n_in,
                              void* d_out, int out_size)
{
    const float* x1 = (const float*)d_in[0];
    const float* x2 = (const float*)d_in[1];
    const float* wq = (const float*)d_in[2];
    const float* bq = (const float*)d_in[3];
    const float* wk = (const float*)d_in[4];
    const float* bk = (const float*)d_in[5];
    const float* wv = (const float*)d_in[6];
    const float* bv = (const float*)d_in[7];
    float* out = (float*)d_out;

    const int n_elem = in_sizes[0];        // B*H*W = 524288
    const int rows   = n_elem / WIDTH;     // B*H   = 2048

    channel_attn_kernel<<<rows, WIDTH>>>(x1, x2, wq, bq, wk, bk, wv, bv,
                                         out, n_elem);
}

// round 4
// speedup vs baseline: 1.1160x; 1.1160x over previous
#include <cuda_runtime.h>
#include <cuda_bf16.h>

// ChannelSelfAttention: B=4,H=512,W=256, C=2.
// Refactor: score s(w,u) = c0(w)*xa[u] + c1(w)*xb[u] + c2(w)   (K folded into q)
//           numerators via A=Σe*xa, B=Σe*xb, D=Σe; V applied once per thread.
// Shared holds only raw {xa,xb} (SoA); inner loop packed with f32x2.

#define WIDTH 256

__device__ __forceinline__ unsigned long long f2_pack(float lo, float hi) {
    unsigned long long r;
    asm("mov.b64 %0, {%1,%2};" : "=l"(r) : "f"(lo), "f"(hi));
    return r;
}
__device__ __forceinline__ void f2_unpack(unsigned long long v, float& lo, float& hi) {
    asm("mov.b64 {%0,%1}, %2;" : "=f"(lo), "=f"(hi) : "l"(v));
}
__device__ __forceinline__ unsigned long long f2_fma(unsigned long long a,
                                                     unsigned long long b,
                                                     unsigned long long c) {
    unsigned long long r;
    asm("fma.rn.f32x2 %0, %1, %2, %3;" : "=l"(r) : "l"(a), "l"(b), "l"(c));
    return r;
}
__device__ __forceinline__ unsigned long long f2_add(unsigned long long a,
                                                     unsigned long long b) {
    unsigned long long r;
    asm("add.rn.f32x2 %0, %1, %2;" : "=l"(r) : "l"(a), "l"(b));
    return r;
}
__device__ __forceinline__ float fast_ex2(float s) {
    float e;
    asm("ex2.approx.ftz.f32 %0, %1;" : "=f"(e) : "f"(s));
    return e;
}

__global__ __launch_bounds__(WIDTH) void channel_attn_kernel(
    const float* __restrict__ x1, const float* __restrict__ x2,
    const float* __restrict__ wq, const float* __restrict__ bq,
    const float* __restrict__ wk, const float* __restrict__ bk,
    const float* __restrict__ wv, const float* __restrict__ bv,
    float* __restrict__ out, int n_elem)
{
    __shared__ __align__(16) float sha[WIDTH];
    __shared__ __align__(16) float shb[WIDTH];

    const int row  = blockIdx.x;
    const int w    = threadIdx.x;
    const int base = row * WIDTH;

    const float xa = x1[base + w];
    const float xb = x2[base + w];
    sha[w] = xa;
    shb[w] = xb;

    // 16 tiny weights, L1/L2 resident
    const float q00 = __ldg(&wq[0]), q01 = __ldg(&wq[1]);
    const float q10 = __ldg(&wq[2]), q11 = __ldg(&wq[3]);
    const float k00 = __ldg(&wk[0]), k01 = __ldg(&wk[1]);
    const float k10 = __ldg(&wk[2]), k11 = __ldg(&wk[3]);
    const float v00 = __ldg(&wv[0]), v01 = __ldg(&wv[1]);
    const float v10 = __ldg(&wv[2]), v11 = __ldg(&wv[3]);
    const float bq0 = __ldg(&bq[0]), bq1 = __ldg(&bq[1]);
    const float bk0 = __ldg(&bk[0]), bk1 = __ldg(&bk[1]);
    const float bv0 = __ldg(&bv[0]), bv1 = __ldg(&bv[1]);

    const float LOG2E = 1.4426950408889634f;
    // q for this w, log2e-folded
    const float a0 = fmaf(q00, xa, fmaf(q01, xb, bq0)) * LOG2E;
    const float a1 = fmaf(q10, xa, fmaf(q11, xb, bq1)) * LOG2E;
    // fold K projection: s = c0*xa[u] + c1*xb[u] + c2
    const float c0 = fmaf(a0, k00, a1 * k10);
    const float c1 = fmaf(a0, k01, a1 * k11);
    const float c2 = fmaf(a0, bk0, a1 * bk1);

    const unsigned long long c0p = f2_pack(c0, c0);
    const unsigned long long c1p = f2_pack(c1, c1);
    const unsigned long long c2p = f2_pack(c2, c2);

    const unsigned sa_base = (unsigned)__cvta_generic_to_shared(sha);
    const unsigned sb_base = (unsigned)__cvta_generic_to_shared(shb);

    __syncthreads();

    // two independent accumulator streams to break RAW chains
    unsigned long long Dx = 0ull, Dy = 0ull;
    unsigned long long Ax = 0ull, Ay = 0ull;
    unsigned long long Bx = 0ull, By = 0ull;

#pragma unroll 4
    for (int u = 0; u < WIDTH; u += 4) {
        unsigned long long xa01, xa23, xb01, xb23;
        asm("ld.shared.v2.b64 {%0,%1}, [%2];"
            : "=l"(xa01), "=l"(xa23) : "r"(sa_base + u * 4));
        asm("ld.shared.v2.b64 {%0,%1}, [%2];"
            : "=l"(xb01), "=l"(xb23) : "r"(sb_base + u * 4));

        unsigned long long s01 = f2_fma(c0p, xa01, f2_fma(c1p, xb01, c2p));
        unsigned long long s23 = f2_fma(c0p, xa23, f2_fma(c1p, xb23, c2p));

        float s0, s1, s2, s3;
        f2_unpack(s01, s0, s1);
        f2_unpack(s23, s2, s3);
        const float e0 = fast_ex2(s0);
        const float e1 = fast_ex2(s1);
        const float e2 = fast_ex2(s2);
        const float e3 = fast_ex2(s3);
        const unsigned long long e01 = f2_pack(e0, e1);
        const unsigned long long e23 = f2_pack(e2, e3);

        Dx = f2_add(Dx, e01);
        Dy = f2_add(Dy, e23);
        Ax = f2_fma(e01, xa01, Ax);
        Ay = f2_fma(e23, xa23, Ay);
        Bx = f2_fma(e01, xb01, Bx);
        By = f2_fma(e23, xb23, By);
    }

    float d0, d1, d2, d3, a0f, a1f, a2f, a3f, b0f, b1f, b2f, b3f;
    f2_unpack(f2_add(Dx, Dy), d0, d1);
    f2_unpack(f2_add(Ax, Ay), a0f, a1f);
    f2_unpack(f2_add(Bx, By), b0f, b1f);
    const float Dv = d0 + d1;
    const float Av = a0f + a1f;
    const float Bv = b0f + b1f;
    (void)d2; (void)d3; (void)a2f; (void)a3f; (void)b2f; (void)b3f;

    const float inv = 1.0f / Dv;
    const float n0  = fmaf(v00, Av, fmaf(v01, Bv, bv0 * Dv));
    const float n1  = fmaf(v10, Av, fmaf(v11, Bv, bv1 * Dv));

    out[base + w]          = fmaf(n0, inv, xa);
    out[n_elem + base + w] = fmaf(n1, inv, xb);
}

extern "C" void kernel_launch(void* const* d_in, const int* in_sizes, int n_in,
                              void* d_out, int out_size)
{
    const float* x1 = (const float*)d_in[0];
    const float* x2 = (const float*)d_in[1];
    const float* wq = (const float*)d_in[2];
    const float* bq = (const float*)d_in[3];
    const float* wk = (const float*)d_in[4];
    const float* bk = (const float*)d_in[5];
    const float* wv = (const float*)d_in[6];
    const float* bv = (const float*)d_in[7];
    float* out = (float*)d_out;

    const int n_elem = in_sizes[0];        // B*H*W = 524288
    const int rows   = n_elem / WIDTH;     // B*H   = 2048

    channel_attn_kernel<<<rows, WIDTH>>>(x1, x2, wq, bq, wk, bk, wv, bv,
                                         out, n_elem);
}